// round 14
// baseline (speedup 1.0000x reference)
#include <cuda_runtime.h>
#include <cuda_bf16.h>
#include <cuda_fp16.h>
#include <cuda_pipeline.h>
#include <mma.h>
#include <cstdint>

using namespace nvcuda;

#define N_V 8192
#define N_E 4096
#define FT  512
#define WN  256   // words per HTB row  (N_V/32)
#define WE  128   // words per HB  row  (N_E/32)

// ---------------- scratch (static device globals; no allocation) ------------
__device__ uint32_t g_HB [N_V * WE];
__device__ uint32_t g_HTB[N_E * WN];
__device__ float    g_y   [N_V];
__device__ float    g_hw  [N_E];
__device__ float    g_dege[N_E];
__device__ float    g_degv[N_V];
__device__ __half   g_zh  [(size_t)N_V * FT];    // fp16 out0 = xW (unscaled)
__device__ __half   g_th  [N_E * FT];            // fp16 t (scaled by 2^-8)
__device__ __nv_bfloat16 g_Ah[(size_t)N_V * FT];
__device__ __nv_bfloat16 g_Al[(size_t)N_V * FT];
__device__ __nv_bfloat16 g_Bh[FT * FT];
__device__ __nv_bfloat16 g_Bl[FT * FT];

// ------------- fused bitmask builder ----------------------------------------
__global__ void __launch_bounds__(256) k_build_bits(const float* __restrict__ H) {
    __shared__ float tile[32][257];
    int e0 = blockIdx.x * 256;
    int n0 = blockIdx.y * 32;
    int t  = threadIdx.x;
#pragma unroll 4
    for (int i = 0; i < 32; i++)
        tile[i][t] = H[(size_t)(n0 + i) * N_E + e0 + t];
    __syncthreads();
    {
        int w = t >> 5, l = t & 31;
#pragma unroll 4
        for (int j = 0; j < 32; j++) {
            int c = w * 32 + j;
            uint32_t m = __ballot_sync(0xffffffffu, tile[l][c] != 0.f);
            if (l == 0) g_HTB[(size_t)(e0 + c) * WN + blockIdx.y] = m;
        }
    }
    {
        int r = t >> 3, wi = t & 7;
        uint32_t bits = 0;
#pragma unroll
        for (int kk = 0; kk < 32; kk++) {
            int k = (wi * 4 + kk) & 31;
            if (tile[r][wi * 32 + k] != 0.f) bits |= 1u << k;
        }
        g_HB[(size_t)(n0 + r) * WE + blockIdx.x * 8 + wi] = bits;
    }
}

// ---------------- y = x @ V --------------------------------------------------
__global__ void __launch_bounds__(256) k_xv(const float* __restrict__ x,
                                            const float* __restrict__ V) {
    int n = blockIdx.x * 8 + (threadIdx.x >> 5);
    int l = threadIdx.x & 31;
    float s = 0.f;
#pragma unroll
    for (int i = 0; i < 16; i++) {
        int f = i * 32 + l;
        s += x[(size_t)n * FT + f] * V[f];
    }
#pragma unroll
    for (int o = 16; o; o >>= 1) s += __shfl_xor_sync(0xffffffffu, s, o);
    if (l == 0) g_y[n] = s;
}

// -------- hw = sigmoid(H^T (xV)), deg_e; write w output ----------------------
__global__ void __launch_bounds__(128) k_hw_dege(float* __restrict__ w_out) {
    int e = blockIdx.x * 4 + (threadIdx.x >> 5);
    int l = threadIdx.x & 31;
    float s = 0.f;
    int cnt = 0;
#pragma unroll
    for (int i = 0; i < 8; i++) {
        uint32_t w = g_HTB[(size_t)e * WN + l * 8 + i];
        cnt += __popc(w);
        int base = (l * 8 + i) * 32;
        while (w) {
            int k = __ffs(w) - 1; w &= w - 1;
            s += g_y[base + k];
        }
    }
#pragma unroll
    for (int o = 16; o; o >>= 1) {
        s   += __shfl_xor_sync(0xffffffffu, s, o);
        cnt += __shfl_xor_sync(0xffffffffu, cnt, o);
    }
    if (l == 0) {
        float hw = 1.f / (1.f + expf(-s));
        g_hw[e]   = hw;
        w_out[e]  = hw;
        g_dege[e] = (float)cnt;
    }
}

// ---------------- deg_v = H @ hw ---------------------------------------------
__global__ void __launch_bounds__(128) k_degv() {
    int n = blockIdx.x * 4 + (threadIdx.x >> 5);
    int l = threadIdx.x & 31;
    float s = 0.f;
#pragma unroll
    for (int jj = 0; jj < 4; jj++) {
        int j = l * 4 + jj;
        uint32_t w = g_HB[(size_t)n * WE + j];
        while (w) { int k = __ffs(w) - 1; w &= w - 1; s += g_hw[j * 32 + k]; }
    }
#pragma unroll
    for (int o = 16; o; o >>= 1) s += __shfl_xor_sync(0xffffffffu, s, o);
    if (l == 0) g_degv[n] = s;
}

// -------- split A = x into bf16 hi/lo ----------------------------------------
__global__ void __launch_bounds__(256) k_splitA(const float* __restrict__ x) {
    int gid = blockIdx.x * blockDim.x + threadIdx.x;
    size_t off = (size_t)gid * 8;
    const float4* p = reinterpret_cast<const float4*>(x + off);
    float v[8];
    float4 a = p[0], b = p[1];
    v[0]=a.x; v[1]=a.y; v[2]=a.z; v[3]=a.w;
    v[4]=b.x; v[5]=b.y; v[6]=b.z; v[7]=b.w;
    __nv_bfloat16 h[8], l[8];
#pragma unroll
    for (int i = 0; i < 8; i++) {
        h[i] = __float2bfloat16(v[i]);
        l[i] = __float2bfloat16(v[i] - __bfloat162float(h[i]));
    }
    *reinterpret_cast<uint4*>(&g_Ah[off]) = *reinterpret_cast<uint4*>(h);
    *reinterpret_cast<uint4*>(&g_Al[off]) = *reinterpret_cast<uint4*>(l);
}

// -------- split B = weight into bf16 hi/lo -----------------------------------
__global__ void __launch_bounds__(256) k_splitB(const float* __restrict__ W) {
    int gid = blockIdx.x * blockDim.x + threadIdx.x;
    size_t off = (size_t)gid * 8;
    const float4* p = reinterpret_cast<const float4*>(W + off);
    float v[8];
    float4 a = p[0], b = p[1];
    v[0]=a.x; v[1]=a.y; v[2]=a.z; v[3]=a.w;
    v[4]=b.x; v[5]=b.y; v[6]=b.z; v[7]=b.w;
    __nv_bfloat16 h[8], l[8];
#pragma unroll
    for (int i = 0; i < 8; i++) {
        h[i] = __float2bfloat16(v[i]);
        l[i] = __float2bfloat16(v[i] - __bfloat162float(h[i]));
    }
    *reinterpret_cast<uint4*>(&g_Bh[off]) = *reinterpret_cast<uint4*>(h);
    *reinterpret_cast<uint4*>(&g_Bl[off]) = *reinterpret_cast<uint4*>(l);
}

// ------ out0 = x @ W, dual-bf16 wmma, 2-stage cp.async pipeline --------------
#define BM 128
#define BN 128
#define BK 32
#define ASZ (BM * (BK + 8))     // 5120 elems per A stage buffer
#define BSZ (BK * (BN + 8))     // 4352 elems per B stage buffer
#define NT  (FT / BK)           // 16 k-tiles

__global__ void __launch_bounds__(256) k_gemm_wmma() {
    extern __shared__ __nv_bfloat16 sm[];
    // layout: Ah[2], Al[2], Bh[2], Bl[2]
    __nv_bfloat16* Ah_s[2] = { sm,                sm + ASZ };
    __nv_bfloat16* Al_s[2] = { sm + 2*ASZ,        sm + 3*ASZ };
    __nv_bfloat16* Bh_s[2] = { sm + 4*ASZ,        sm + 4*ASZ + BSZ };
    __nv_bfloat16* Bl_s[2] = { sm + 4*ASZ + 2*BSZ, sm + 4*ASZ + 3*BSZ };

    int bm = blockIdx.y * BM;
    int bn = blockIdx.x * BN;
    int tid = threadIdx.x;
    int wid = tid >> 5;
    int wy = wid >> 2;
    int wx = wid & 3;

    // per-thread copy slots (2 per tile): A row/col, B row/col
    int a_row0 = tid >> 2,          a_col = (tid & 3) * 8;
    int a_row1 = (tid + 256) >> 2;  // second half
    int b_row0 = tid >> 4,          b_col = (tid & 15) * 8;
    int b_row1 = (tid + 256) >> 4;

    auto load_stage = [&](int s, int k0) {
        __pipeline_memcpy_async(&Ah_s[s][a_row0 * (BK+8) + a_col],
                                &g_Ah[(size_t)(bm + a_row0) * FT + k0 + a_col], 16);
        __pipeline_memcpy_async(&Ah_s[s][a_row1 * (BK+8) + a_col],
                                &g_Ah[(size_t)(bm + a_row1) * FT + k0 + a_col], 16);
        __pipeline_memcpy_async(&Al_s[s][a_row0 * (BK+8) + a_col],
                                &g_Al[(size_t)(bm + a_row0) * FT + k0 + a_col], 16);
        __pipeline_memcpy_async(&Al_s[s][a_row1 * (BK+8) + a_col],
                                &g_Al[(size_t)(bm + a_row1) * FT + k0 + a_col], 16);
        __pipeline_memcpy_async(&Bh_s[s][b_row0 * (BN+8) + b_col],
                                &g_Bh[(size_t)(k0 + b_row0) * FT + bn + b_col], 16);
        __pipeline_memcpy_async(&Bh_s[s][b_row1 * (BN+8) + b_col],
                                &g_Bh[(size_t)(k0 + b_row1) * FT + bn + b_col], 16);
        __pipeline_memcpy_async(&Bl_s[s][b_row0 * (BN+8) + b_col],
                                &g_Bl[(size_t)(k0 + b_row0) * FT + bn + b_col], 16);
        __pipeline_memcpy_async(&Bl_s[s][b_row1 * (BN+8) + b_col],
                                &g_Bl[(size_t)(k0 + b_row1) * FT + bn + b_col], 16);
    };

    wmma::fragment<wmma::accumulator, 16, 16, 16, float> acc[4][2];
#pragma unroll
    for (int i = 0; i < 4; i++)
#pragma unroll
        for (int j = 0; j < 2; j++) wmma::fill_fragment(acc[i][j], 0.f);

    load_stage(0, 0);
    __pipeline_commit();

    for (int kt = 0; kt < NT; kt++) {
        int cur = kt & 1;
        if (kt + 1 < NT) {
            load_stage(cur ^ 1, (kt + 1) * BK);
            __pipeline_commit();
            __pipeline_wait_prior(1);
        } else {
            __pipeline_wait_prior(0);
        }
        __syncthreads();    // stage `cur` visible to all warps

        const __nv_bfloat16* pAh = Ah_s[cur];
        const __nv_bfloat16* pAl = Al_s[cur];
        const __nv_bfloat16* pBh = Bh_s[cur];
        const __nv_bfloat16* pBl = Bl_s[cur];
#pragma unroll
        for (int kk = 0; kk < 2; kk++) {
            wmma::fragment<wmma::matrix_a, 16, 16, 16, __nv_bfloat16, wmma::row_major> afh[4], afl[4];
            wmma::fragment<wmma::matrix_b, 16, 16, 16, __nv_bfloat16, wmma::row_major> bfh[2], bfl[2];
#pragma unroll
            for (int i = 0; i < 4; i++) {
                wmma::load_matrix_sync(afh[i], &pAh[(wy * 64 + i * 16) * (BK+8) + kk * 16], BK + 8);
                wmma::load_matrix_sync(afl[i], &pAl[(wy * 64 + i * 16) * (BK+8) + kk * 16], BK + 8);
            }
#pragma unroll
            for (int j = 0; j < 2; j++) {
                wmma::load_matrix_sync(bfh[j], &pBh[(kk * 16) * (BN+8) + wx * 32 + j * 16], BN + 8);
                wmma::load_matrix_sync(bfl[j], &pBl[(kk * 16) * (BN+8) + wx * 32 + j * 16], BN + 8);
            }
#pragma unroll
            for (int i = 0; i < 4; i++)
#pragma unroll
                for (int j = 0; j < 2; j++) {
                    wmma::mma_sync(acc[i][j], afh[i], bfh[j], acc[i][j]);
                    wmma::mma_sync(acc[i][j], afh[i], bfl[j], acc[i][j]);
                    wmma::mma_sync(acc[i][j], afl[i], bfh[j], acc[i][j]);
                }
        }
        __syncthreads();    // all reads of `cur` done before kt+2 overwrites it
    }
#pragma unroll
    for (int i = 0; i < 4; i++) {
        int row = bm + wy * 64 + i * 16;
#pragma unroll
        for (int j = 0; j < 2; j++) {
            int col = bn + wx * 32 + j * 16;
            wmma::fragment<wmma::accumulator, 16, 16, 16, __half> hacc;
#pragma unroll
            for (int q = 0; q < hacc.num_elements; q++)
                hacc.x[q] = __float2half(acc[i][j].x[q]);
            wmma::store_matrix_sync(&g_zh[(size_t)row * FT + col], hacc,
                                    FT, wmma::mem_row_major);
        }
    }
}
#define GEMM_SMEM_BYTES ((4 * ASZ + 4 * BSZ) * (int)sizeof(__nv_bfloat16))

// 8 halves (uint4) -> fp32 FMA into two float4 accumulators
__device__ __forceinline__ void fma8(float4& a0, float4& a1, float dv, uint4 v) {
    float2 p0 = __half22float2(*reinterpret_cast<__half2*>(&v.x));
    float2 p1 = __half22float2(*reinterpret_cast<__half2*>(&v.y));
    float2 p2 = __half22float2(*reinterpret_cast<__half2*>(&v.z));
    float2 p3 = __half22float2(*reinterpret_cast<__half2*>(&v.w));
    a0.x += dv * p0.x; a0.y += dv * p0.y; a0.z += dv * p1.x; a0.w += dv * p1.y;
    a1.x += dv * p2.x; a1.y += dv * p2.y; a1.z += dv * p3.x; a1.w += dv * p3.y;
}
__device__ __forceinline__ void add8(float4& a0, float4& a1, uint4 v) {
    float2 p0 = __half22float2(*reinterpret_cast<__half2*>(&v.x));
    float2 p1 = __half22float2(*reinterpret_cast<__half2*>(&v.y));
    float2 p2 = __half22float2(*reinterpret_cast<__half2*>(&v.z));
    float2 p3 = __half22float2(*reinterpret_cast<__half2*>(&v.w));
    a0.x += p0.x; a0.y += p0.y; a0.z += p1.x; a0.w += p1.y;
    a1.x += p2.x; a1.y += p2.y; a1.z += p3.x; a1.w += p3.y;
}

// ------ t = (w*deg_e/256) ⊙ H^T @ (deg_v ⊙ out0)  (16B gather, 2 groups) -----
#define CAP_E 512
__global__ void __launch_bounds__(128) k_edge_gather_t() {
    int e    = blockIdx.x;
    int tid  = threadIdx.x;
    int feat = tid & 63;
    int grp  = tid >> 6;
    __shared__ int   idx[CAP_E];
    __shared__ float dvs[CAP_E];
    __shared__ float red[64 * 8];
    __shared__ int   cnt;
    if (tid == 0) cnt = 0;
    __syncthreads();
    for (int j = tid; j < WN; j += 128) {
        uint32_t w = g_HTB[(size_t)e * WN + j];
        if (w) {
            int pos = atomicAdd(&cnt, __popc(w));
            while (w) {
                int k = __ffs(w) - 1; w &= w - 1;
                if (pos < CAP_E) idx[pos] = j * 32 + k;
                pos++;
            }
        }
    }
    __syncthreads();
    int m = cnt < CAP_E ? cnt : CAP_E;
    for (int i = tid; i < m; i += 128) dvs[i] = g_degv[idx[i]];
    __syncthreads();

    const uint4* z4 = reinterpret_cast<const uint4*>(g_zh);
    float4 a0 = {0.f, 0.f, 0.f, 0.f}, a1 = {0.f, 0.f, 0.f, 0.f};
    int i = grp;
    for (; i + 6 < m; i += 8) {
        uint4 v0 = z4[(size_t)idx[i]     * 64 + feat];
        uint4 v1 = z4[(size_t)idx[i + 2] * 64 + feat];
        uint4 v2 = z4[(size_t)idx[i + 4] * 64 + feat];
        uint4 v3 = z4[(size_t)idx[i + 6] * 64 + feat];
        fma8(a0, a1, dvs[i],     v0);
        fma8(a0, a1, dvs[i + 2], v1);
        fma8(a0, a1, dvs[i + 4], v2);
        fma8(a0, a1, dvs[i + 6], v3);
    }
    for (; i < m; i += 2)
        fma8(a0, a1, dvs[i], z4[(size_t)idx[i] * 64 + feat]);

    if (grp == 1) {
        *reinterpret_cast<float4*>(&red[feat * 8])     = a0;
        *reinterpret_cast<float4*>(&red[feat * 8 + 4]) = a1;
    }
    __syncthreads();
    if (grp == 0) {
        float4 b0 = *reinterpret_cast<float4*>(&red[feat * 8]);
        float4 b1 = *reinterpret_cast<float4*>(&red[feat * 8 + 4]);
        float s = g_hw[e] * g_dege[e] * (1.f / 256.f);
        __half2 r[4];
        r[0] = __floats2half2_rn(s * (a0.x + b0.x), s * (a0.y + b0.y));
        r[1] = __floats2half2_rn(s * (a0.z + b0.z), s * (a0.w + b0.w));
        r[2] = __floats2half2_rn(s * (a1.x + b1.x), s * (a1.y + b1.y));
        r[3] = __floats2half2_rn(s * (a1.z + b1.z), s * (a1.w + b1.w));
        reinterpret_cast<uint4*>(g_th)[(size_t)e * 64 + feat] =
            *reinterpret_cast<uint4*>(r);
    }
}

// ------------ out = deg_v*256 ⊙ (H @ t) + bias  (16B gather, 2 groups) -------
#define CAP_V 320
__global__ void __launch_bounds__(128) k_vertex_gather(const float* __restrict__ bias,
                                                       float* __restrict__ out) {
    int n    = blockIdx.x;
    int tid  = threadIdx.x;
    int feat = tid & 63;
    int grp  = tid >> 6;
    __shared__ int   idx[CAP_V];
    __shared__ float red[64 * 8];
    __shared__ int   cnt;
    if (tid == 0) cnt = 0;
    __syncthreads();
    if (tid < WE) {
        uint32_t w = g_HB[(size_t)n * WE + tid];
        if (w) {
            int pos = atomicAdd(&cnt, __popc(w));
            while (w) {
                int k = __ffs(w) - 1; w &= w - 1;
                if (pos < CAP_V) idx[pos] = tid * 32 + k;
                pos++;
            }
        }
    }
    __syncthreads();
    int m = cnt < CAP_V ? cnt : CAP_V;

    const uint4* t4 = reinterpret_cast<const uint4*>(g_th);
    float4 a0 = {0.f, 0.f, 0.f, 0.f}, a1 = {0.f, 0.f, 0.f, 0.f};
    int i = grp;
    for (; i + 6 < m; i += 8) {
        uint4 v0 = t4[(size_t)idx[i]     * 64 + feat];
        uint4 v1 = t4[(size_t)idx[i + 2] * 64 + feat];
        uint4 v2 = t4[(size_t)idx[i + 4] * 64 + feat];
        uint4 v3 = t4[(size_t)idx[i + 6] * 64 + feat];
        add8(a0, a1, v0); add8(a0, a1, v1);
        add8(a0, a1, v2); add8(a0, a1, v3);
    }
    for (; i < m; i += 2)
        add8(a0, a1, t4[(size_t)idx[i] * 64 + feat]);

    if (grp == 1) {
        *reinterpret_cast<float4*>(&red[feat * 8])     = a0;
        *reinterpret_cast<float4*>(&red[feat * 8 + 4]) = a1;
    }
    __syncthreads();
    if (grp == 0) {
        float4 b0 = *reinterpret_cast<float4*>(&red[feat * 8]);
        float4 b1 = *reinterpret_cast<float4*>(&red[feat * 8 + 4]);
        float dv = g_degv[n] * 256.f;
        const float4* bias4 = reinterpret_cast<const float4*>(bias);
        float4 c0 = bias4[feat * 2], c1 = bias4[feat * 2 + 1];
        float4 r0 = {dv * (a0.x + b0.x) + c0.x, dv * (a0.y + b0.y) + c0.y,
                     dv * (a0.z + b0.z) + c0.z, dv * (a0.w + b0.w) + c0.w};
        float4 r1 = {dv * (a1.x + b1.x) + c1.x, dv * (a1.y + b1.y) + c1.y,
                     dv * (a1.z + b1.z) + c1.z, dv * (a1.w + b1.w) + c1.w};
        float4* o4 = reinterpret_cast<float4*>(out + (size_t)n * FT);
        o4[feat * 2]     = r0;
        o4[feat * 2 + 1] = r1;
    }
}

// ---------------- launch -----------------------------------------------------
extern "C" void kernel_launch(void* const* d_in, const int* in_sizes, int n_in,
                              void* d_out, int out_size) {
    const float* x      = (const float*)d_in[0];
    const float* H      = (const float*)d_in[1];
    const float* weight = (const float*)d_in[2];
    const float* V      = (const float*)d_in[3];
    const float* bias   = (const float*)d_in[4];
    float* out   = (float*)d_out;
    float* w_out = (float*)d_out + (size_t)N_V * FT;

    static cudaStream_t s2 = nullptr;
    static cudaEvent_t  evF = nullptr, evY = nullptr, evJ = nullptr;
    if (s2 == nullptr) {
        cudaStreamCreateWithFlags(&s2, cudaStreamNonBlocking);
        cudaEventCreateWithFlags(&evF, cudaEventDisableTiming);
        cudaEventCreateWithFlags(&evY, cudaEventDisableTiming);
        cudaEventCreateWithFlags(&evJ, cudaEventDisableTiming);
        cudaFuncSetAttribute(k_gemm_wmma,
                             cudaFuncAttributeMaxDynamicSharedMemorySize,
                             GEMM_SMEM_BYTES);
    }

    // Fork: xv + GEMM chain on side stream (independent of bitmask build).
    cudaEventRecord(evF, 0);
    cudaStreamWaitEvent(s2, evF, 0);
    k_xv       <<<N_V / 8, 256, 0, s2>>>(x, V);
    cudaEventRecord(evY, s2);
    k_splitA   <<<((size_t)N_V * FT / 8) / 256, 256, 0, s2>>>(x);
    k_splitB   <<<(FT * FT / 8) / 256, 256, 0, s2>>>(weight);
    k_gemm_wmma<<<dim3(FT / BN, N_V / BM), 256, GEMM_SMEM_BYTES, s2>>>();
    cudaEventRecord(evJ, s2);

    // Main stream: bitmask chain.
    k_build_bits<<<dim3(N_E / 256, N_V / 32), 256>>>(H);
    cudaStreamWaitEvent(0, evY, 0);     // hw needs y = xV
    k_hw_dege   <<<N_E / 4, 128>>>(w_out);
    k_degv      <<<N_V / 4, 128>>>();

    // Join, then the two dependent gathers.
    cudaStreamWaitEvent(0, evJ, 0);
    k_edge_gather_t<<<N_E, 128>>>();
    k_vertex_gather<<<N_V, 128>>>(bias, out);
}

// round 17
// speedup vs baseline: 1.0018x; 1.0018x over previous
#include <cuda_runtime.h>
#include <cuda_bf16.h>
#include <cuda_fp16.h>
#include <cuda_pipeline.h>
#include <mma.h>
#include <cstdint>

using namespace nvcuda;

#define N_V 8192
#define N_E 4096
#define FT  512
#define WN  256   // words per HTB row  (N_V/32)
#define WE  128   // words per HB  row  (N_E/32)

// ---------------- scratch (static device globals; no allocation) ------------
__device__ uint32_t g_HB [N_V * WE];
__device__ uint32_t g_HTB[N_E * WN];
__device__ float    g_y   [N_V];
__device__ float    g_hw  [N_E];
__device__ float    g_dege[N_E];
__device__ float    g_degv[N_V];
__device__ __half   g_zh  [(size_t)N_V * FT];    // fp16 out0 = xW (unscaled)
__device__ __half   g_th  [N_E * FT];            // fp16 t (scaled by 2^-8)
__device__ __nv_bfloat16 g_Ah[(size_t)N_V * FT];
__device__ __nv_bfloat16 g_Al[(size_t)N_V * FT];
__device__ __nv_bfloat16 g_Bh[FT * FT];
__device__ __nv_bfloat16 g_Bl[FT * FT];

// ------------- HB builder: pure streaming, coalesced -------------------------
__global__ void __launch_bounds__(256) k_build_HB(const float* __restrict__ H) {
    int idx = blockIdx.x * blockDim.x + threadIdx.x;   // n*WE + w
    int n = idx >> 7;
    int w = idx & 127;
    const float4* p = reinterpret_cast<const float4*>(H + (size_t)n * N_E + w * 32);
    uint32_t bits = 0;
#pragma unroll
    for (int i = 0; i < 8; i++) {
        float4 v = p[i];
        if (v.x != 0.f) bits |= 1u << (i * 4 + 0);
        if (v.y != 0.f) bits |= 1u << (i * 4 + 1);
        if (v.z != 0.f) bits |= 1u << (i * 4 + 2);
        if (v.w != 0.f) bits |= 1u << (i * 4 + 3);
    }
    g_HB[idx] = bits;
}

// ------------- HTB = bit-transpose of HB (32x32 blocks, warp shuffles) -------
__global__ void __launch_bounds__(256) k_transpose_bits() {
    int cta  = blockIdx.x;                 // 4096 CTAs
    int nb   = cta >> 4;                   // 0..255 (vertex word-block)
    int wid  = threadIdx.x >> 5;
    int lane = threadIdx.x & 31;
    int eb   = (cta & 15) * 8 + wid;       // 0..127 (edge word-block)

    uint32_t x = g_HB[(size_t)(nb * 32 + lane) * WE + eb];
#pragma unroll
    for (int i = 16; i >= 1; i >>= 1) {
        uint32_t m = (i == 16) ? 0x0000FFFFu : (i == 8) ? 0x00FF00FFu :
                     (i == 4)  ? 0x0F0F0F0Fu : (i == 2) ? 0x33333333u : 0x55555555u;
        uint32_t y = __shfl_xor_sync(0xffffffffu, x, i);
        if (lane & i) x = (x & ~m) | ((y & ~m) >> i);
        else          x = (x &  m) | ((y &  m) << i);
    }
    // lane j now holds bits over the 32 vertices for edge eb*32+j
    g_HTB[(size_t)(eb * 32 + lane) * WN + nb] = x;
}

// ---------------- y = x @ V --------------------------------------------------
__global__ void __launch_bounds__(256) k_xv(const float* __restrict__ x,
                                            const float* __restrict__ V) {
    int n = blockIdx.x * 8 + (threadIdx.x >> 5);
    int l = threadIdx.x & 31;
    float s = 0.f;
#pragma unroll
    for (int i = 0; i < 16; i++) {
        int f = i * 32 + l;
        s += x[(size_t)n * FT + f] * V[f];
    }
#pragma unroll
    for (int o = 16; o; o >>= 1) s += __shfl_xor_sync(0xffffffffu, s, o);
    if (l == 0) g_y[n] = s;
}

// -------- hw = sigmoid(H^T (xV)), deg_e; write w output ----------------------
__global__ void __launch_bounds__(128) k_hw_dege(float* __restrict__ w_out) {
    int e = blockIdx.x * 4 + (threadIdx.x >> 5);
    int l = threadIdx.x & 31;
    float s = 0.f;
    int cnt = 0;
#pragma unroll
    for (int i = 0; i < 8; i++) {
        uint32_t w = g_HTB[(size_t)e * WN + l * 8 + i];
        cnt += __popc(w);
        int base = (l * 8 + i) * 32;
        while (w) {
            int k = __ffs(w) - 1; w &= w - 1;
            s += g_y[base + k];
        }
    }
#pragma unroll
    for (int o = 16; o; o >>= 1) {
        s   += __shfl_xor_sync(0xffffffffu, s, o);
        cnt += __shfl_xor_sync(0xffffffffu, cnt, o);
    }
    if (l == 0) {
        float hw = 1.f / (1.f + expf(-s));
        g_hw[e]   = hw;
        w_out[e]  = hw;
        g_dege[e] = (float)cnt;
    }
}

// ---------------- deg_v = H @ hw ---------------------------------------------
__global__ void __launch_bounds__(128) k_degv() {
    int n = blockIdx.x * 4 + (threadIdx.x >> 5);
    int l = threadIdx.x & 31;
    float s = 0.f;
#pragma unroll
    for (int jj = 0; jj < 4; jj++) {
        int j = l * 4 + jj;
        uint32_t w = g_HB[(size_t)n * WE + j];
        while (w) { int k = __ffs(w) - 1; w &= w - 1; s += g_hw[j * 32 + k]; }
    }
#pragma unroll
    for (int o = 16; o; o >>= 1) s += __shfl_xor_sync(0xffffffffu, s, o);
    if (l == 0) g_degv[n] = s;
}

// -------- split A = x into bf16 hi/lo ----------------------------------------
__global__ void __launch_bounds__(256) k_splitA(const float* __restrict__ x) {
    int gid = blockIdx.x * blockDim.x + threadIdx.x;
    size_t off = (size_t)gid * 8;
    const float4* p = reinterpret_cast<const float4*>(x + off);
    float v[8];
    float4 a = p[0], b = p[1];
    v[0]=a.x; v[1]=a.y; v[2]=a.z; v[3]=a.w;
    v[4]=b.x; v[5]=b.y; v[6]=b.z; v[7]=b.w;
    __nv_bfloat16 h[8], l[8];
#pragma unroll
    for (int i = 0; i < 8; i++) {
        h[i] = __float2bfloat16(v[i]);
        l[i] = __float2bfloat16(v[i] - __bfloat162float(h[i]));
    }
    *reinterpret_cast<uint4*>(&g_Ah[off]) = *reinterpret_cast<uint4*>(h);
    *reinterpret_cast<uint4*>(&g_Al[off]) = *reinterpret_cast<uint4*>(l);
}

// -------- split B = weight into bf16 hi/lo -----------------------------------
__global__ void __launch_bounds__(256) k_splitB(const float* __restrict__ W) {
    int gid = blockIdx.x * blockDim.x + threadIdx.x;
    size_t off = (size_t)gid * 8;
    const float4* p = reinterpret_cast<const float4*>(W + off);
    float v[8];
    float4 a = p[0], b = p[1];
    v[0]=a.x; v[1]=a.y; v[2]=a.z; v[3]=a.w;
    v[4]=b.x; v[5]=b.y; v[6]=b.z; v[7]=b.w;
    __nv_bfloat16 h[8], l[8];
#pragma unroll
    for (int i = 0; i < 8; i++) {
        h[i] = __float2bfloat16(v[i]);
        l[i] = __float2bfloat16(v[i] - __bfloat162float(h[i]));
    }
    *reinterpret_cast<uint4*>(&g_Bh[off]) = *reinterpret_cast<uint4*>(h);
    *reinterpret_cast<uint4*>(&g_Bl[off]) = *reinterpret_cast<uint4*>(l);
}

// ------ out0 = x @ W, dual-bf16 wmma, 2-stage cp.async, BM128xBN64 -----------
#define BM 128
#define BN 64
#define BK 32
#define ASZ (BM * (BK + 8))     // 5120 elems
#define BSZ (BK * (BN + 8))     // 2304 elems
#define NT  (FT / BK)           // 16 k-tiles

__global__ void __launch_bounds__(256) k_gemm_wmma() {
    extern __shared__ __nv_bfloat16 sm[];
    __nv_bfloat16* Ah_s[2] = { sm,                 sm + ASZ };
    __nv_bfloat16* Al_s[2] = { sm + 2*ASZ,         sm + 3*ASZ };
    __nv_bfloat16* Bh_s[2] = { sm + 4*ASZ,         sm + 4*ASZ + BSZ };
    __nv_bfloat16* Bl_s[2] = { sm + 4*ASZ + 2*BSZ, sm + 4*ASZ + 3*BSZ };

    int bm = blockIdx.y * BM;
    int bn = blockIdx.x * BN;
    int tid = threadIdx.x;
    int wid = tid >> 5;
    int wy = wid >> 1;      // 0..3 -> 32 rows each
    int wx = wid & 1;       // 0..1 -> 32 cols each

    int a_row0 = tid >> 2,  a_col = (tid & 3) * 8;   // rows 0..63
    int a_row1 = a_row0 + 64;
    int b_row  = tid >> 3,  b_col = (tid & 7) * 8;   // rows 0..31

    auto load_stage = [&](int s, int k0) {
        __pipeline_memcpy_async(&Ah_s[s][a_row0 * (BK+8) + a_col],
                                &g_Ah[(size_t)(bm + a_row0) * FT + k0 + a_col], 16);
        __pipeline_memcpy_async(&Ah_s[s][a_row1 * (BK+8) + a_col],
                                &g_Ah[(size_t)(bm + a_row1) * FT + k0 + a_col], 16);
        __pipeline_memcpy_async(&Al_s[s][a_row0 * (BK+8) + a_col],
                                &g_Al[(size_t)(bm + a_row0) * FT + k0 + a_col], 16);
        __pipeline_memcpy_async(&Al_s[s][a_row1 * (BK+8) + a_col],
                                &g_Al[(size_t)(bm + a_row1) * FT + k0 + a_col], 16);
        __pipeline_memcpy_async(&Bh_s[s][b_row * (BN+8) + b_col],
                                &g_Bh[(size_t)(k0 + b_row) * FT + bn + b_col], 16);
        __pipeline_memcpy_async(&Bl_s[s][b_row * (BN+8) + b_col],
                                &g_Bl[(size_t)(k0 + b_row) * FT + bn + b_col], 16);
    };

    wmma::fragment<wmma::accumulator, 16, 16, 16, float> acc[2][2];
#pragma unroll
    for (int i = 0; i < 2; i++)
#pragma unroll
        for (int j = 0; j < 2; j++) wmma::fill_fragment(acc[i][j], 0.f);

    load_stage(0, 0);
    __pipeline_commit();

    for (int kt = 0; kt < NT; kt++) {
        int cur = kt & 1;
        if (kt + 1 < NT) {
            load_stage(cur ^ 1, (kt + 1) * BK);
            __pipeline_commit();
            __pipeline_wait_prior(1);
        } else {
            __pipeline_wait_prior(0);
        }
        __syncthreads();

        const __nv_bfloat16* pAh = Ah_s[cur];
        const __nv_bfloat16* pAl = Al_s[cur];
        const __nv_bfloat16* pBh = Bh_s[cur];
        const __nv_bfloat16* pBl = Bl_s[cur];
#pragma unroll
        for (int kk = 0; kk < 2; kk++) {
            wmma::fragment<wmma::matrix_a, 16, 16, 16, __nv_bfloat16, wmma::row_major> afh[2], afl[2];
            wmma::fragment<wmma::matrix_b, 16, 16, 16, __nv_bfloat16, wmma::row_major> bfh[2], bfl[2];
#pragma unroll
            for (int i = 0; i < 2; i++) {
                wmma::load_matrix_sync(afh[i], &pAh[(wy * 32 + i * 16) * (BK+8) + kk * 16], BK + 8);
                wmma::load_matrix_sync(afl[i], &pAl[(wy * 32 + i * 16) * (BK+8) + kk * 16], BK + 8);
            }
#pragma unroll
            for (int j = 0; j < 2; j++) {
                wmma::load_matrix_sync(bfh[j], &pBh[(kk * 16) * (BN+8) + wx * 32 + j * 16], BN + 8);
                wmma::load_matrix_sync(bfl[j], &pBl[(kk * 16) * (BN+8) + wx * 32 + j * 16], BN + 8);
            }
#pragma unroll
            for (int i = 0; i < 2; i++)
#pragma unroll
                for (int j = 0; j < 2; j++) {
                    wmma::mma_sync(acc[i][j], afh[i], bfh[j], acc[i][j]);
                    wmma::mma_sync(acc[i][j], afh[i], bfl[j], acc[i][j]);
                    wmma::mma_sync(acc[i][j], afl[i], bfh[j], acc[i][j]);
                }
        }
        __syncthreads();
    }
#pragma unroll
    for (int i = 0; i < 2; i++) {
        int row = bm + wy * 32 + i * 16;
#pragma unroll
        for (int j = 0; j < 2; j++) {
            int col = bn + wx * 32 + j * 16;
            wmma::fragment<wmma::accumulator, 16, 16, 16, __half> hacc;
#pragma unroll
            for (int q = 0; q < hacc.num_elements; q++)
                hacc.x[q] = __float2half(acc[i][j].x[q]);
            wmma::store_matrix_sync(&g_zh[(size_t)row * FT + col], hacc,
                                    FT, wmma::mem_row_major);
        }
    }
}
#define GEMM_SMEM_BYTES ((4 * ASZ + 4 * BSZ) * (int)sizeof(__nv_bfloat16))

// 8 halves (uint4) -> fp32 FMA into two float4 accumulators
__device__ __forceinline__ void fma8(float4& a0, float4& a1, float dv, uint4 v) {
    float2 p0 = __half22float2(*reinterpret_cast<__half2*>(&v.x));
    float2 p1 = __half22float2(*reinterpret_cast<__half2*>(&v.y));
    float2 p2 = __half22float2(*reinterpret_cast<__half2*>(&v.z));
    float2 p3 = __half22float2(*reinterpret_cast<__half2*>(&v.w));
    a0.x += dv * p0.x; a0.y += dv * p0.y; a0.z += dv * p1.x; a0.w += dv * p1.y;
    a1.x += dv * p2.x; a1.y += dv * p2.y; a1.z += dv * p3.x; a1.w += dv * p3.y;
}
__device__ __forceinline__ void add8(float4& a0, float4& a1, uint4 v) {
    float2 p0 = __half22float2(*reinterpret_cast<__half2*>(&v.x));
    float2 p1 = __half22float2(*reinterpret_cast<__half2*>(&v.y));
    float2 p2 = __half22float2(*reinterpret_cast<__half2*>(&v.z));
    float2 p3 = __half22float2(*reinterpret_cast<__half2*>(&v.w));
    a0.x += p0.x; a0.y += p0.y; a0.z += p1.x; a0.w += p1.y;
    a1.x += p2.x; a1.y += p2.y; a1.z += p3.x; a1.w += p3.y;
}

// ------ t = (w*deg_e/256) ⊙ H^T @ (deg_v ⊙ out0)  (16B gather, 2 groups) -----
#define CAP_E 512
__global__ void __launch_bounds__(128) k_edge_gather_t() {
    int e    = blockIdx.x;
    int tid  = threadIdx.x;
    int feat = tid & 63;
    int grp  = tid >> 6;
    __shared__ int   idx[CAP_E];
    __shared__ float dvs[CAP_E];
    __shared__ float red[64 * 8];
    __shared__ int   cnt;
    if (tid == 0) cnt = 0;
    __syncthreads();
    for (int j = tid; j < WN; j += 128) {
        uint32_t w = g_HTB[(size_t)e * WN + j];
        if (w) {
            int pos = atomicAdd(&cnt, __popc(w));
            while (w) {
                int k = __ffs(w) - 1; w &= w - 1;
                if (pos < CAP_E) idx[pos] = j * 32 + k;
                pos++;
            }
        }
    }
    __syncthreads();
    int m = cnt < CAP_E ? cnt : CAP_E;
    for (int i = tid; i < m; i += 128) dvs[i] = g_degv[idx[i]];
    __syncthreads();

    const uint4* z4 = reinterpret_cast<const uint4*>(g_zh);
    float4 a0 = {0.f, 0.f, 0.f, 0.f}, a1 = {0.f, 0.f, 0.f, 0.f};
    int i = grp;
    for (; i + 6 < m; i += 8) {
        uint4 v0 = z4[(size_t)idx[i]     * 64 + feat];
        uint4 v1 = z4[(size_t)idx[i + 2] * 64 + feat];
        uint4 v2 = z4[(size_t)idx[i + 4] * 64 + feat];
        uint4 v3 = z4[(size_t)idx[i + 6] * 64 + feat];
        fma8(a0, a1, dvs[i],     v0);
        fma8(a0, a1, dvs[i + 2], v1);
        fma8(a0, a1, dvs[i + 4], v2);
        fma8(a0, a1, dvs[i + 6], v3);
    }
    for (; i < m; i += 2)
        fma8(a0, a1, dvs[i], z4[(size_t)idx[i] * 64 + feat]);

    if (grp == 1) {
        *reinterpret_cast<float4*>(&red[feat * 8])     = a0;
        *reinterpret_cast<float4*>(&red[feat * 8 + 4]) = a1;
    }
    __syncthreads();
    if (grp == 0) {
        float4 b0 = *reinterpret_cast<float4*>(&red[feat * 8]);
        float4 b1 = *reinterpret_cast<float4*>(&red[feat * 8 + 4]);
        float s = g_hw[e] * g_dege[e] * (1.f / 256.f);
        __half2 r[4];
        r[0] = __floats2half2_rn(s * (a0.x + b0.x), s * (a0.y + b0.y));
        r[1] = __floats2half2_rn(s * (a0.z + b0.z), s * (a0.w + b0.w));
        r[2] = __floats2half2_rn(s * (a1.x + b1.x), s * (a1.y + b1.y));
        r[3] = __floats2half2_rn(s * (a1.z + b1.z), s * (a1.w + b1.w));
        reinterpret_cast<uint4*>(g_th)[(size_t)e * 64 + feat] =
            *reinterpret_cast<uint4*>(r);
    }
}

// ------------ out = deg_v*256 ⊙ (H @ t) + bias  (16B gather, 2 groups) -------
#define CAP_V 320
__global__ void __launch_bounds__(128) k_vertex_gather(const float* __restrict__ bias,
                                                       float* __restrict__ out) {
    int n    = blockIdx.x;
    int tid  = threadIdx.x;
    int feat = tid & 63;
    int grp  = tid >> 6;
    __shared__ int   idx[CAP_V];
    __shared__ float red[64 * 8];
    __shared__ int   cnt;
    if (tid == 0) cnt = 0;
    __syncthreads();
    if (tid < WE) {
        uint32_t w = g_HB[(size_t)n * WE + tid];
        if (w) {
            int pos = atomicAdd(&cnt, __popc(w));
            while (w) {
                int k = __ffs(w) - 1; w &= w - 1;
                if (pos < CAP_V) idx[pos] = tid * 32 + k;
                pos++;
            }
        }
    }
    __syncthreads();
    int m = cnt < CAP_V ? cnt : CAP_V;

    const uint4* t4 = reinterpret_cast<const uint4*>(g_th);
    float4 a0 = {0.f, 0.f, 0.f, 0.f}, a1 = {0.f, 0.f, 0.f, 0.f};
    int i = grp;
    for (; i + 6 < m; i += 8) {
        uint4 v0 = t4[(size_t)idx[i]     * 64 + feat];
        uint4 v1 = t4[(size_t)idx[i + 2] * 64 + feat];
        uint4 v2 = t4[(size_t)idx[i + 4] * 64 + feat];
        uint4 v3 = t4[(size_t)idx[i + 6] * 64 + feat];
        add8(a0, a1, v0); add8(a0, a1, v1);
        add8(a0, a1, v2); add8(a0, a1, v3);
    }
    for (; i < m; i += 2)
        add8(a0, a1, t4[(size_t)idx[i] * 64 + feat]);

    if (grp == 1) {
        *reinterpret_cast<float4*>(&red[feat * 8])     = a0;
        *reinterpret_cast<float4*>(&red[feat * 8 + 4]) = a1;
    }
    __syncthreads();
    if (grp == 0) {
        float4 b0 = *reinterpret_cast<float4*>(&red[feat * 8]);
        float4 b1 = *reinterpret_cast<float4*>(&red[feat * 8 + 4]);
        float dv = g_degv[n] * 256.f;
        const float4* bias4 = reinterpret_cast<const float4*>(bias);
        float4 c0 = bias4[feat * 2], c1 = bias4[feat * 2 + 1];
        float4 r0 = {dv * (a0.x + b0.x) + c0.x, dv * (a0.y + b0.y) + c0.y,
                     dv * (a0.z + b0.z) + c0.z, dv * (a0.w + b0.w) + c0.w};
        float4 r1 = {dv * (a1.x + b1.x) + c1.x, dv * (a1.y + b1.y) + c1.y,
                     dv * (a1.z + b1.z) + c1.z, dv * (a1.w + b1.w) + c1.w};
        float4* o4 = reinterpret_cast<float4*>(out + (size_t)n * FT);
        o4[feat * 2]     = r0;
        o4[feat * 2 + 1] = r1;
    }
}

// ---------------- launch -----------------------------------------------------
extern "C" void kernel_launch(void* const* d_in, const int* in_sizes, int n_in,
                              void* d_out, int out_size) {
    const float* x      = (const float*)d_in[0];
    const float* H      = (const float*)d_in[1];
    const float* weight = (const float*)d_in[2];
    const float* V      = (const float*)d_in[3];
    const float* bias   = (const float*)d_in[4];
    float* out   = (float*)d_out;
    float* w_out = (float*)d_out + (size_t)N_V * FT;

    static cudaStream_t s2 = nullptr;
    static cudaEvent_t  evF = nullptr, evY = nullptr, evJ = nullptr;
    if (s2 == nullptr) {
        cudaStreamCreateWithFlags(&s2, cudaStreamNonBlocking);
        cudaEventCreateWithFlags(&evF, cudaEventDisableTiming);
        cudaEventCreateWithFlags(&evY, cudaEventDisableTiming);
        cudaEventCreateWithFlags(&evJ, cudaEventDisableTiming);
        cudaFuncSetAttribute(k_gemm_wmma,
                             cudaFuncAttributeMaxDynamicSharedMemorySize,
                             GEMM_SMEM_BYTES);
    }

    // Fork: xv + GEMM chain on side stream (independent of bitmask build).
    cudaEventRecord(evF, 0);
    cudaStreamWaitEvent(s2, evF, 0);
    k_xv       <<<N_V / 8, 256, 0, s2>>>(x, V);
    cudaEventRecord(evY, s2);
    k_splitA   <<<((size_t)N_V * FT / 8) / 256, 256, 0, s2>>>(x);
    k_splitB   <<<(FT * FT / 8) / 256, 256, 0, s2>>>(weight);
    k_gemm_wmma<<<dim3(FT / BN, N_V / BM), 256, GEMM_SMEM_BYTES, s2>>>();
    cudaEventRecord(evJ, s2);

    // Main stream: bitmask chain (HB stream-build, then bit-transpose to HTB).
    k_build_HB      <<<(N_V * WE) / 256, 256>>>(H);
    k_transpose_bits<<<4096, 256>>>();
    cudaStreamWaitEvent(0, evY, 0);     // hw needs y = xV
    k_hw_dege   <<<N_E / 4, 128>>>(w_out);
    k_degv      <<<N_V / 4, 128>>>();

    // Join, then the two dependent gathers.
    cudaStreamWaitEvent(0, evJ, 0);
    k_edge_gather_t<<<N_E, 128>>>();
    k_vertex_gather<<<N_V, 128>>>(bias, out);
}